// round 9
// baseline (speedup 1.0000x reference)
#include <cuda_runtime.h>

#define RES 1024
#define NUM_ROOMS 8
#define N_AGENTS 5000000
#define PLANE (RES * RES)

// Scratch (no device allocation allowed)
__device__ __align__(16) float g_ex[NUM_ROOMS * RES];  // exp(-(x_i-cx)^2/(2sx^2))
__device__ __align__(16) float g_ey[NUM_ROOMS * RES];  // exp(-(y_j-cy)^2/(2sy^2))
__device__ int g_maxbits;

// ---------------------------------------------------------------------------
// Kernel 1 (R4-proven, unchanged): zero flow region of d_out (float4), build
// Gaussian tables, reset max. Doubles as the bin-warming / drain-absorbing
// pass right before the atomic-heavy histogram.
// ---------------------------------------------------------------------------
__global__ void k_init(const float* __restrict__ rooms, float4* __restrict__ flow4) {
    int tid = blockIdx.x * blockDim.x + threadIdx.x;
    if (tid < PLANE / 4) flow4[tid] = make_float4(0.f, 0.f, 0.f, 0.f);
    if (tid < NUM_ROOMS * RES) {
        int r = tid >> 10, i = tid & (RES - 1);
        float lin = (float)i * (1.0f / (RES - 1));
        float cx = rooms[r * 4 + 0], sx = rooms[r * 4 + 2];
        float cy = rooms[r * 4 + 1], sy = rooms[r * 4 + 3];
        float dx = lin - cx, dy = lin - cy;
        g_ex[tid] = __expf(-dx * dx / (2.0f * sx * sx));
        g_ey[tid] = __expf(-dy * dy / (2.0f * sy * sy));
    }
    if (tid == 0) g_maxbits = 0;
}

// ---------------------------------------------------------------------------
// Kernel 2: histogram WITH fused max tracking.
// atomicAdd returns the pre-increment count; global max = max(returns) + 1.
// One block reduce + one atomicMax per block replaces the whole k_max pass.
// ---------------------------------------------------------------------------
__global__ void k_hist(const float4* __restrict__ pos4, float* __restrict__ flow, int npairs) {
    __shared__ float smax[8];
    int tid = blockIdx.x * blockDim.x + threadIdx.x;

    float m = 0.0f;
    if (tid < npairs) {
        float4 p = pos4[tid];
        int ix0 = min(max((int)(p.x * (float)RES), 0), RES - 1);
        int iy0 = min(max((int)(p.y * (float)RES), 0), RES - 1);
        int ix1 = min(max((int)(p.z * (float)RES), 0), RES - 1);
        int iy1 = min(max((int)(p.w * (float)RES), 0), RES - 1);
        float o0 = atomicAdd(&flow[(ix0 << 10) | iy0], 1.0f);
        float o1 = atomicAdd(&flow[(ix1 << 10) | iy1], 1.0f);
        m = fmaxf(o0, o1) + 1.0f;   // post-increment counts this thread created
    }

    #pragma unroll
    for (int off = 16; off > 0; off >>= 1)
        m = fmaxf(m, __shfl_xor_sync(0xffffffffu, m, off));
    int lane = threadIdx.x & 31, warp = threadIdx.x >> 5;
    if (lane == 0) smax[warp] = m;
    __syncthreads();
    if (threadIdx.x == 0) {
        float bm = smax[0];
        #pragma unroll
        for (int w = 1; w < 8; w++) bm = fmaxf(bm, smax[w]);
        // valid int-compare: all values are non-negative floats
        atomicMax(&g_maxbits, __float_as_int(bm));
    }
}

// ---------------------------------------------------------------------------
// Kernel 3 (R4-proven, unchanged): fused normalize + layout.
//   blocks [0, 1024)    : normalize one flow row each (float4), in place
//   blocks [1024, 5120) : (room-pair rp, row i); each thread writes rooms
//                         rp and rp+4 at one float4 column.
// ---------------------------------------------------------------------------
__global__ void __launch_bounds__(256) k_final(const float4* __restrict__ wall4,
                                               float* __restrict__ out) {
    float4* out4 = (float4*)out;
    float4* flow4 = out4 + NUM_ROOMS * (PLANE / 4);
    int bid = blockIdx.x;

    if (bid < RES) {
        float inv = 1.0f / (__int_as_float(g_maxbits) + 1e-6f);
        int idx4 = (bid << 8) + threadIdx.x;
        float4 f = flow4[idx4];
        f.x *= inv; f.y *= inv; f.z *= inv; f.w *= inv;
        flow4[idx4] = f;
        return;
    }

    int b = bid - RES;              // 0..4095
    int rp = b >> 10;               // room pair 0..3 (rooms rp, rp+4)
    int i  = b & (RES - 1);         // row
    int q  = threadIdx.x;           // float4 col 0..255
    int idx4 = (i << 8) + q;

    float4 w = wall4[idx4];
    w.x = 1.0f - w.x; w.y = 1.0f - w.y; w.z = 1.0f - w.z; w.w = 1.0f - w.w;

    const float4* ey4 = (const float4*)g_ey;

    int r0 = rp, r1 = rp + 4;
    float ex0 = g_ex[(r0 << 10) + i];
    float ex1 = g_ex[(r1 << 10) + i];
    float4 e0 = ey4[(r0 << 8) + q];
    float4 e1 = ey4[(r1 << 8) + q];

    float4 o0, o1;
    o0.x = ex0 * e0.x * w.x;  o0.y = ex0 * e0.y * w.y;
    o0.z = ex0 * e0.z * w.z;  o0.w = ex0 * e0.w * w.w;
    o1.x = ex1 * e1.x * w.x;  o1.y = ex1 * e1.y * w.y;
    o1.z = ex1 * e1.z * w.z;  o1.w = ex1 * e1.w * w.w;

    out4[r0 * (PLANE / 4) + idx4] = o0;
    out4[r1 * (PLANE / 4) + idx4] = o1;
}

// ---------------------------------------------------------------------------
extern "C" void kernel_launch(void* const* d_in, const int* in_sizes, int n_in,
                              void* d_out, int out_size) {
    const float* pos   = (const float*)d_in[0];   // [5000000, 2]
    const float* rooms = (const float*)d_in[1];   // [8, 4]
    const float* wall  = (const float*)d_in[2];   // [1024, 1024]
    float* out = (float*)d_out;                   // 8 planes + flow plane
    float* flow = out + NUM_ROOMS * PLANE;

    // 1) zero flow + tables + max reset (R4-proven; warms bin lines in L2)
    k_init<<<(PLANE / 4 + 255) / 256, 256>>>(rooms, (float4*)flow);

    // 2) histogram with fused max tracking (k_max deleted)
    int npairs = N_AGENTS / 2;   // 2,500,000
    k_hist<<<(npairs + 255) / 256, 256>>>((const float4*)pos, flow, npairs);

    // 3) fused normalize + layout (R4-proven)
    k_final<<<RES + 4 * RES, 256>>>((const float4*)wall, out);
}

// round 10
// speedup vs baseline: 1.3371x; 1.3371x over previous
#include <cuda_runtime.h>

#define RES 1024
#define NUM_ROOMS 8
#define N_AGENTS 5000000
#define PLANE (RES * RES)

// Scratch (no device allocation allowed)
__device__ __align__(16) float g_ex[NUM_ROOMS * RES];  // exp(-(x_i-cx)^2/(2sx^2))
__device__ __align__(16) float g_ey[NUM_ROOMS * RES];  // exp(-(y_j-cy)^2/(2sy^2))
__device__ int g_maxbits;
__device__ float4 g_sink;   // never actually written; defeats DCE on prefetch

// ---------------------------------------------------------------------------
// Kernel 1: zero flow region (float4), build tables, reset max.
// NEW: also touch the wall tensor to pull it into L2 while this kernel's
// issue slots are idle — k_final's wall loads become L2 hits.
// ---------------------------------------------------------------------------
__global__ void k_init(const float* __restrict__ rooms,
                       const float4* __restrict__ wall4,
                       float4* __restrict__ flow4) {
    int tid = blockIdx.x * blockDim.x + threadIdx.x;
    if (tid < PLANE / 4) {
        flow4[tid] = make_float4(0.f, 0.f, 0.f, 0.f);
        float4 w = wall4[tid];                       // L2 warm
        if (__float_as_int(w.x) == 0x7f800001)      // NaN payload: never true
            g_sink = w;                              // keeps the load live
    }
    if (tid < NUM_ROOMS * RES) {
        int r = tid >> 10, i = tid & (RES - 1);
        float lin = (float)i * (1.0f / (RES - 1));
        float cx = rooms[r * 4 + 0], sx = rooms[r * 4 + 2];
        float cy = rooms[r * 4 + 1], sy = rooms[r * 4 + 3];
        float dx = lin - cx, dy = lin - cy;
        g_ex[tid] = __expf(-dx * dx / (2.0f * sx * sx));
        g_ey[tid] = __expf(-dy * dy / (2.0f * sy * sy));
    }
    if (tid == 0) g_maxbits = 0;
}

// ---------------------------------------------------------------------------
// Kernel 2: histogram, 4 agents per thread (2 independent float4 loads,
// 4 independent fire-and-forget RED.ADD.F32 — NO return values).
// ---------------------------------------------------------------------------
__global__ void k_hist(const float4* __restrict__ pos4, float* __restrict__ flow,
                       int half_quads) {
    int t = blockIdx.x * blockDim.x + threadIdx.x;
    if (t >= half_quads) return;
    float4 a = pos4[t];
    float4 b = pos4[t + half_quads];

    int ix0 = min(max((int)(a.x * (float)RES), 0), RES - 1);
    int iy0 = min(max((int)(a.y * (float)RES), 0), RES - 1);
    int ix1 = min(max((int)(a.z * (float)RES), 0), RES - 1);
    int iy1 = min(max((int)(a.w * (float)RES), 0), RES - 1);
    int ix2 = min(max((int)(b.x * (float)RES), 0), RES - 1);
    int iy2 = min(max((int)(b.y * (float)RES), 0), RES - 1);
    int ix3 = min(max((int)(b.z * (float)RES), 0), RES - 1);
    int iy3 = min(max((int)(b.w * (float)RES), 0), RES - 1);

    atomicAdd(&flow[(ix0 << 10) | iy0], 1.0f);
    atomicAdd(&flow[(ix1 << 10) | iy1], 1.0f);
    atomicAdd(&flow[(ix2 << 10) | iy2], 1.0f);
    atomicAdd(&flow[(ix3 << 10) | iy3], 1.0f);
}

// ---------------------------------------------------------------------------
// Kernel 3 (R4-proven, unchanged): global max of flow.
// ---------------------------------------------------------------------------
__global__ void k_max(const float4* __restrict__ flow4) {
    __shared__ float smax[8];
    float m = 0.0f;
    int stride = gridDim.x * blockDim.x;
    for (int t = blockIdx.x * blockDim.x + threadIdx.x; t < PLANE / 4; t += stride) {
        float4 v = flow4[t];
        m = fmaxf(m, fmaxf(fmaxf(v.x, v.y), fmaxf(v.z, v.w)));
    }
    #pragma unroll
    for (int off = 16; off > 0; off >>= 1)
        m = fmaxf(m, __shfl_xor_sync(0xffffffffu, m, off));
    int lane = threadIdx.x & 31, warp = threadIdx.x >> 5;
    if (lane == 0) smax[warp] = m;
    __syncthreads();
    if (threadIdx.x == 0) {
        float bm = smax[0];
        #pragma unroll
        for (int w = 1; w < 8; w++) bm = fmaxf(bm, smax[w]);
        atomicMax(&g_maxbits, __float_as_int(bm));
    }
}

// ---------------------------------------------------------------------------
// Kernel 4 (R4-proven, unchanged): fused normalize + layout.
//   blocks [0, 1024)    : normalize one flow row each (float4), in place
//   blocks [1024, 5120) : (room-pair rp, row i); thread writes rooms rp, rp+4.
// ---------------------------------------------------------------------------
__global__ void __launch_bounds__(256) k_final(const float4* __restrict__ wall4,
                                               float* __restrict__ out) {
    float4* out4 = (float4*)out;
    float4* flow4 = out4 + NUM_ROOMS * (PLANE / 4);
    int bid = blockIdx.x;

    if (bid < RES) {
        float inv = 1.0f / (__int_as_float(g_maxbits) + 1e-6f);
        int idx4 = (bid << 8) + threadIdx.x;
        float4 f = flow4[idx4];
        f.x *= inv; f.y *= inv; f.z *= inv; f.w *= inv;
        flow4[idx4] = f;
        return;
    }

    int b = bid - RES;              // 0..4095
    int rp = b >> 10;               // room pair 0..3 (rooms rp, rp+4)
    int i  = b & (RES - 1);         // row
    int q  = threadIdx.x;           // float4 col 0..255
    int idx4 = (i << 8) + q;

    float4 w = wall4[idx4];
    w.x = 1.0f - w.x; w.y = 1.0f - w.y; w.z = 1.0f - w.z; w.w = 1.0f - w.w;

    const float4* ey4 = (const float4*)g_ey;

    int r0 = rp, r1 = rp + 4;
    float ex0 = g_ex[(r0 << 10) + i];
    float ex1 = g_ex[(r1 << 10) + i];
    float4 e0 = ey4[(r0 << 8) + q];
    float4 e1 = ey4[(r1 << 8) + q];

    float4 o0, o1;
    o0.x = ex0 * e0.x * w.x;  o0.y = ex0 * e0.y * w.y;
    o0.z = ex0 * e0.z * w.z;  o0.w = ex0 * e0.w * w.w;
    o1.x = ex1 * e1.x * w.x;  o1.y = ex1 * e1.y * w.y;
    o1.z = ex1 * e1.z * w.z;  o1.w = ex1 * e1.w * w.w;

    out4[r0 * (PLANE / 4) + idx4] = o0;
    out4[r1 * (PLANE / 4) + idx4] = o1;
}

// ---------------------------------------------------------------------------
extern "C" void kernel_launch(void* const* d_in, const int* in_sizes, int n_in,
                              void* d_out, int out_size) {
    const float* pos   = (const float*)d_in[0];   // [5000000, 2]
    const float* rooms = (const float*)d_in[1];   // [8, 4]
    const float* wall  = (const float*)d_in[2];   // [1024, 1024]
    float* out = (float*)d_out;                   // 8 planes + flow plane
    float* flow = out + NUM_ROOMS * PLANE;

    // 1) zero flow + tables + warm wall into L2
    k_init<<<(PLANE / 4 + 255) / 256, 256>>>(rooms, (const float4*)wall, (float4*)flow);

    // 2) histogram: 4 agents/thread, returnless REDs
    int half_quads = N_AGENTS / 4;   // 1,250,000 threads, 2 float4 loads each
    k_hist<<<(half_quads + 255) / 256, 256>>>((const float4*)pos, flow, half_quads);

    // 3) max reduce (R4-proven)
    k_max<<<1184, 256>>>((const float4*)flow);

    // 4) fused normalize + layout (R4-proven)
    k_final<<<RES + 4 * RES, 256>>>((const float4*)wall, out);
}

// round 11
// speedup vs baseline: 1.4105x; 1.0548x over previous
#include <cuda_runtime.h>

#define RES 1024
#define NUM_ROOMS 8
#define N_AGENTS 5000000
#define PLANE (RES * RES)

// Scratch (no device allocation allowed)
__device__ __align__(16) float g_ex[NUM_ROOMS * RES];  // exp(-(x_i-cx)^2/(2sx^2))
__device__ __align__(16) float g_ey[NUM_ROOMS * RES];  // exp(-(y_j-cy)^2/(2sy^2))
__device__ int g_maxbits;

// ---------------------------------------------------------------------------
// Kernel 1 (R4 body): zero flow (float4), build tables, reset max.
// Triggers immediately so k_hist can launch and run its independent
// position-load preamble concurrently.
// ---------------------------------------------------------------------------
__global__ void k_init(const float* __restrict__ rooms, float4* __restrict__ flow4) {
    cudaTriggerProgrammaticLaunchCompletion();
    int tid = blockIdx.x * blockDim.x + threadIdx.x;
    if (tid < PLANE / 4) flow4[tid] = make_float4(0.f, 0.f, 0.f, 0.f);
    if (tid < NUM_ROOMS * RES) {
        int r = tid >> 10, i = tid & (RES - 1);
        float lin = (float)i * (1.0f / (RES - 1));
        float cx = rooms[r * 4 + 0], sx = rooms[r * 4 + 2];
        float cy = rooms[r * 4 + 1], sy = rooms[r * 4 + 3];
        float dx = lin - cx, dy = lin - cy;
        g_ex[tid] = __expf(-dx * dx / (2.0f * sx * sx));
        g_ey[tid] = __expf(-dy * dy / (2.0f * sy * sy));
    }
    if (tid == 0) g_maxbits = 0;
}

// ---------------------------------------------------------------------------
// Kernel 2 (R4 body + PDL): preamble loads positions & computes bin indices
// (independent of k_init), THEN waits for init's bins, then fires returnless
// REDs. Triggers at end so k_max's launch gap is hidden in the drain.
// ---------------------------------------------------------------------------
__global__ void k_hist(const float4* __restrict__ pos4, float* __restrict__ flow,
                       int npairs) {
    int tid = blockIdx.x * blockDim.x + threadIdx.x;
    bool act = tid < npairs;
    float4 p = make_float4(0.f, 0.f, 0.f, 0.f);
    if (act) p = pos4[tid];                       // overlaps with k_init

    int ix0 = min(max((int)(p.x * (float)RES), 0), RES - 1);
    int iy0 = min(max((int)(p.y * (float)RES), 0), RES - 1);
    int ix1 = min(max((int)(p.z * (float)RES), 0), RES - 1);
    int iy1 = min(max((int)(p.w * (float)RES), 0), RES - 1);

    cudaGridDependencySynchronize();              // bins zeroed & visible
    if (act) {
        atomicAdd(&flow[(ix0 << 10) | iy0], 1.0f);
        atomicAdd(&flow[(ix1 << 10) | iy1], 1.0f);
    }
    cudaTriggerProgrammaticLaunchCompletion();
}

// ---------------------------------------------------------------------------
// Kernel 3 (R4 body + PDL): trigger FIRST so k_final's layout blocks (which
// don't depend on the max) launch and overlap this read pass; then wait for
// hist counts and reduce.
// ---------------------------------------------------------------------------
__global__ void k_max(const float4* __restrict__ flow4) {
    cudaTriggerProgrammaticLaunchCompletion();
    cudaGridDependencySynchronize();              // hist counts complete
    __shared__ float smax[8];
    float m = 0.0f;
    int stride = gridDim.x * blockDim.x;
    for (int t = blockIdx.x * blockDim.x + threadIdx.x; t < PLANE / 4; t += stride) {
        float4 v = flow4[t];
        m = fmaxf(m, fmaxf(fmaxf(v.x, v.y), fmaxf(v.z, v.w)));
    }
    #pragma unroll
    for (int off = 16; off > 0; off >>= 1)
        m = fmaxf(m, __shfl_xor_sync(0xffffffffu, m, off));
    int lane = threadIdx.x & 31, warp = threadIdx.x >> 5;
    if (lane == 0) smax[warp] = m;
    __syncthreads();
    if (threadIdx.x == 0) {
        float bm = smax[0];
        #pragma unroll
        for (int w = 1; w < 8; w++) bm = fmaxf(bm, smax[w]);
        atomicMax(&g_maxbits, __float_as_int(bm));
    }
}

// ---------------------------------------------------------------------------
// Kernel 4 (R4 body + PDL): layout blocks run with NO dependency wait
// (tables/wall were final two completed kernels ago) — they overlap k_max.
// Normalize blocks wait for k_max's grid before reading g_maxbits/flow.
// ---------------------------------------------------------------------------
__global__ void __launch_bounds__(256) k_final(const float4* __restrict__ wall4,
                                               float* __restrict__ out) {
    float4* out4 = (float4*)out;
    float4* flow4 = out4 + NUM_ROOMS * (PLANE / 4);
    int bid = blockIdx.x;

    if (bid < RES) {
        cudaGridDependencySynchronize();          // g_maxbits + counts final
        float inv = 1.0f / (__int_as_float(g_maxbits) + 1e-6f);
        int idx4 = (bid << 8) + threadIdx.x;
        float4 f = flow4[idx4];
        f.x *= inv; f.y *= inv; f.z *= inv; f.w *= inv;
        flow4[idx4] = f;
        return;
    }

    int b = bid - RES;              // 0..4095
    int rp = b >> 10;               // room pair 0..3 (rooms rp, rp+4)
    int i  = b & (RES - 1);         // row
    int q  = threadIdx.x;           // float4 col 0..255
    int idx4 = (i << 8) + q;

    float4 w = wall4[idx4];
    w.x = 1.0f - w.x; w.y = 1.0f - w.y; w.z = 1.0f - w.z; w.w = 1.0f - w.w;

    const float4* ey4 = (const float4*)g_ey;

    int r0 = rp, r1 = rp + 4;
    float ex0 = g_ex[(r0 << 10) + i];
    float ex1 = g_ex[(r1 << 10) + i];
    float4 e0 = ey4[(r0 << 8) + q];
    float4 e1 = ey4[(r1 << 8) + q];

    float4 o0, o1;
    o0.x = ex0 * e0.x * w.x;  o0.y = ex0 * e0.y * w.y;
    o0.z = ex0 * e0.z * w.z;  o0.w = ex0 * e0.w * w.w;
    o1.x = ex1 * e1.x * w.x;  o1.y = ex1 * e1.y * w.y;
    o1.z = ex1 * e1.z * w.z;  o1.w = ex1 * e1.w * w.w;

    out4[r0 * (PLANE / 4) + idx4] = o0;
    out4[r1 * (PLANE / 4) + idx4] = o1;
}

// ---------------------------------------------------------------------------
template <typename... Args>
static void launch_pdl(void (*kern)(Args...), int grid, int block, Args... args) {
    cudaLaunchConfig_t cfg = {};
    cfg.gridDim = dim3(grid);
    cfg.blockDim = dim3(block);
    cudaLaunchAttribute attr[1];
    attr[0].id = cudaLaunchAttributeProgrammaticStreamSerialization;
    attr[0].val.programmaticStreamSerializationAllowed = 1;
    cfg.attrs = attr;
    cfg.numAttrs = 1;
    cudaLaunchKernelEx(&cfg, kern, args...);
}

extern "C" void kernel_launch(void* const* d_in, const int* in_sizes, int n_in,
                              void* d_out, int out_size) {
    const float* pos   = (const float*)d_in[0];   // [5000000, 2]
    const float* rooms = (const float*)d_in[1];   // [8, 4]
    const float* wall  = (const float*)d_in[2];   // [1024, 1024]
    float* out = (float*)d_out;                   // 8 planes + flow plane
    float* flow = out + NUM_ROOMS * PLANE;

    int npairs = N_AGENTS / 2;   // 2,500,000

    // 1) init (normal launch)
    k_init<<<(PLANE / 4 + 255) / 256, 256>>>(rooms, (float4*)flow);

    // 2) hist — PDL: position loads overlap init
    launch_pdl(k_hist, (npairs + 255) / 256, 256,
               (const float4*)pos, flow, npairs);

    // 3) max — PDL: launch hidden in hist drain
    launch_pdl(k_max, 1184, 256, (const float4*)flow);

    // 4) final — PDL: layout blocks overlap k_max
    launch_pdl(k_final, RES + 4 * RES, 256, (const float4*)wall, out);
}